// round 15
// baseline (speedup 1.0000x reference)
#include <cuda_runtime.h>
#include <cuda_fp16.h>
#include <cstdint>

#define T_DIM 200
#define B_DIM 2048
#define I_DIM 128
#define H_DIM 128
#define K_LAB 4
#define S_TILE 32
#define GRID   1024            // each CTA runs TWO independent batch pipelines (one per group)
#define THREADS 256
#define XP     68              // pair-row stride (u32 words): conflict-free A-frag reads
#define BI     (B_DIM * I_DIM)

// ---- shared memory layout (4-byte word offsets) ----
// WP shared by both groups; everything else per group (stride GW).
// csg/x2g OVERLAY xlg/xmg (dead after the c-tile build; a group barrier separates).
#define SM_WP   0               // 16*8*32 uint2 = 8192 words (32 KB W1 pack, fp16)
#define GW      3712            // per-group region size
#define G_XB    0               // 2176: staging / c-phase A-tile (hi rows 0-15, lo rows 16-31)
#define G_PB    2176            // 512: p exchange
#define G_XL    2688            // 512 (later overlaid by csg = 0.5*(c+b1))
#define G_XM    3200            // 512 (later overlaid by x2g)
#define G_CS    G_XL
#define G_X2    G_XM
#define SM_TOT  (8192 + 2*GW)   // 15616 words = 62464 B  (x3 CTAs = 187 KB)

#define W1_FRAGS  (16 * 8 * 32)    // 4096
#define W23_FRAGS (2 * 16 * 8 * 32)

// W1 packed as fp16 B fragments: [nt(16)][kc(8)][lane(32)] -> (wh0, wh1)
__device__ uint2 g_Wpack[W1_FRAGS];
// W2 (pass 0) and W3 (pass 1) packed the same way: [p(2)][nt(16)][kc(8)][lane(32)]
__device__ uint2 g_W23pack[W23_FRAGS];

__device__ __forceinline__ uint32_t pack_f16x2(float e_even, float e_odd) {
    uint32_t r;
    asm("cvt.rn.f16x2.f32 %0, %1, %2;" : "=r"(r) : "f"(e_odd), "f"(e_even));
    return r;
}
__device__ __forceinline__ float2 unpack_f16x2(uint32_t u) {
    __half2 h = *reinterpret_cast<__half2*>(&u);
    return __half22float2(h);
}
__device__ __forceinline__ float tanhf_fast(float z) {
    float t;
    asm("tanh.approx.f32 %0, %1;" : "=f"(t) : "f"(z));
    return t;
}
__device__ __forceinline__ void mma_f16(float* c,
                                        uint32_t a0, uint32_t a1, uint32_t a2, uint32_t a3,
                                        uint32_t b0, uint32_t b1) {
    asm volatile(
        "mma.sync.aligned.m16n8k16.row.col.f32.f16.f16.f32 "
        "{%0,%1,%2,%3}, {%4,%5,%6,%7}, {%8,%9}, {%0,%1,%2,%3};"
        : "+f"(c[0]), "+f"(c[1]), "+f"(c[2]), "+f"(c[3])
        : "r"(a0), "r"(a1), "r"(a2), "r"(a3), "r"(b0), "r"(b1));
}
__device__ __forceinline__ void ldsm4(uint32_t& r0, uint32_t& r1, uint32_t& r2,
                                      uint32_t& r3, uint32_t a) {
    asm volatile("ldmatrix.sync.aligned.m8n8.x4.shared.b16 {%0,%1,%2,%3}, [%4];"
                 : "=r"(r0), "=r"(r1), "=r"(r2), "=r"(r3) : "r"(a));
}
__device__ __forceinline__ void barg(int id) {
    asm volatile("bar.sync %0, 128;" :: "r"(id) : "memory");
}

// ---------------- pack kernel: W1/W2/W3 -> fp16 B-fragment layouts ----------------
__global__ void pack_kernel(const float* __restrict__ w1_w,
                            const float* __restrict__ w2_w,
                            const float* __restrict__ w3_w) {
    int idx = blockIdx.x * blockDim.x + threadIdx.x;   // 0 .. W1_FRAGS + W23_FRAGS - 1
    if (idx >= W1_FRAGS + W23_FRAGS) return;

    const float* src;
    uint2* dst;
    int kc, lane, nt;
    if (idx < W1_FRAGS) {             // W1: [nt(16)][kc(8)][lane(32)]
        lane = idx & 31; kc = (idx >> 5) & 7; nt = (idx >> 8) & 15;
        src = w1_w; dst = g_Wpack + idx;
    } else {                          // W2/W3: [p(2)][nt(16)][kc(8)][lane(32)]
        int i2 = idx - W1_FRAGS;
        lane = i2 & 31; kc = (i2 >> 5) & 7; nt = (i2 >> 8) & 15;
        int p = i2 >> 12;
        src = p ? w3_w : w2_w;
        dst = g_W23pack + i2;
    }
    int n  = nt * 8 + (lane >> 2);
    int k0 = kc * 16 + 2 * (lane & 3);
    const float* wr = src + n * I_DIM;
    uint2 v;
    v.x = pack_f16x2(wr[k0],     wr[k0 + 1]);
    v.y = pack_f16x2(wr[k0 + 8], wr[k0 + 9]);
    *dst = v;
}

// ---------------- main fused kernel ----------------
__global__ void __launch_bounds__(THREADS, 3)
fused_r15_kernel(const float* __restrict__ inputs,
                 const int*   __restrict__ lengths,
                 const float* __restrict__ w0,
                 const float* __restrict__ w1_b,
                 float* __restrict__ out)
{
    extern __shared__ float sm[];
    uint32_t* smu = reinterpret_cast<uint32_t*>(sm);

    const int tid   = threadIdx.x;
    const int lane  = tid & 31;
    const int grp   = tid >> 7;          // group 0/1: independent batch pipeline
    const int nh    = (tid >> 5) & 3;    // warp within group: h quarter
    const int g     = lane >> 2;         // row group 0..7
    const int qc    = lane & 3;          // col class 0..3
    const int local = tid & 127;         // index within group

    const int b     = blockIdx.x * 2 + grp;
    const int len   = lengths[b];
    const int start = max(len - K_LAB, 0);
    const int nk    = min(len, K_LAB);

    // per-group smem regions
    float*    gbase = sm + 8192 + grp * GW;
    uint32_t* xb    = smu + 8192 + grp * GW + G_XB;
    float*    pbg   = gbase + G_PB;
    float*    csg   = gbase + G_CS;   // overlays xlg
    float*    x2g   = gbase + G_X2;   // overlays xmg
    float*    xlg   = gbase + G_XL;
    float*    xmg   = gbase + G_XM;
    const int bar   = 1 + grp;

    // ---- copy packed W1 into smem (both groups cooperate; 2048 uint4) ----
    uint4* wp4g = reinterpret_cast<uint4*>(g_Wpack);
    uint4* wp4s = reinterpret_cast<uint4*>(smu + SM_WP);
    #pragma unroll
    for (int i = 0; i < 8; i++)
        wp4s[tid + i * THREADS] = wp4g[tid + i * THREADS];
    const uint2* wp2 = reinterpret_cast<const uint2*>(smu + SM_WP);

    // ---- hoist w0 (pre-halved) fragments ----
    float w0h[4][2];
    float w0s = 0.f;
    #pragma unroll
    for (int nt = 0; nt < 4; nt++)
        #pragma unroll
        for (int c = 0; c < 2; c++) {
            int h = nh * 32 + nt * 8 + 2 * qc + c;
            w0h[nt][c] = 0.5f * w0[h];
            w0s += w0h[nt][c];
        }

    // ldmatrix lane address pattern (word offset within a 32-row buffer)
    const uint32_t arow = (uint32_t)((lane & 15) * XP + (lane >> 4) * 4);

    __syncthreads();   // W pack visible to both groups (only cross-group sync)

    // ---- prefix sum + labeled snapshots: one thread per feature, register-only ----
    {
        const int i = local;
        const float* ip = inputs + (size_t)b * I_DIM + i;
        float a0 = 0.f, a1 = 0.f, a2 = 0.f, a3 = 0.f;
        float a4 = 0.f, a5 = 0.f, a6 = 0.f, a7 = 0.f;
        int s = 0;
        for (; s + 8 <= start; s += 8) {
            a0 += ip[(size_t)(s    ) * BI];
            a1 += ip[(size_t)(s + 1) * BI];
            a2 += ip[(size_t)(s + 2) * BI];
            a3 += ip[(size_t)(s + 3) * BI];
            a4 += ip[(size_t)(s + 4) * BI];
            a5 += ip[(size_t)(s + 5) * BI];
            a6 += ip[(size_t)(s + 6) * BI];
            a7 += ip[(size_t)(s + 7) * BI];
        }
        float acc = ((a0 + a1) + (a2 + a3)) + ((a4 + a5) + (a6 + a7));
        for (; s < start; s++)
            acc += ip[(size_t)s * BI];
        #pragma unroll
        for (int k = 0; k < K_LAB; k++) {
            float xv = 0.f, mv = 0.f;
            if (k < nk) {
                xv = ip[(size_t)(start + k) * BI];
                acc += xv;
                mv = acc / (float)(start + k + 1);
            }
            xlg[k * 128 + i] = xv;
            xmg[k * 128 + i] = mv;
        }
    }
    barg(bar);

    // ---- build c-phase A tile in group buffer: hi rows 0-15, lo rows 16-31 ----
    // data rows 0-3 = xlab, 4-7 = xm, rows 8-15 = 0 (both hi and lo halves)
    {
        const int r   = local >> 4;          // 0..7
        const int t16 = local & 15;
        #pragma unroll
        for (int u = 0; u < 2; u++) {
            const int t32 = t16 * 2 + u;
            const float4 v = *reinterpret_cast<const float4*>(
                &(r < 4 ? xlg[r * 128] : xmg[(r - 4) * 128]) + t32 * 4);
            uint32_t h0 = pack_f16x2(v.x, v.y);
            uint32_t h1 = pack_f16x2(v.z, v.w);
            float2 f0 = unpack_f16x2(h0);
            float2 f1 = unpack_f16x2(h1);
            uint32_t l0 = pack_f16x2(v.x - f0.x, v.y - f0.y);
            uint32_t l1 = pack_f16x2(v.z - f1.x, v.w - f1.y);
            int p = r * XP + t32 * 2;
            *reinterpret_cast<uint2*>(xb + p)           = make_uint2(h0, h1);   // hi row r
            *reinterpret_cast<uint2*>(xb + 16 * XP + p) = make_uint2(l0, l1);   // lo row r
            int z = (8 + r) * XP + t32 * 2;
            *reinterpret_cast<uint2*>(xb + z)           = make_uint2(0u, 0u);
            *reinterpret_cast<uint2*>(xb + 16 * XP + z) = make_uint2(0u, 0u);
        }
    }
    barg(bar);   // all xlg/xmg reads complete -> csg/x2g overlay is now safe

    // ---- c[k][h] via MMA (2-pass hi/lo A): pass0 B=W2 (-> x2), pass1 B=W3 (rows 4-7 -> wms) ----
    {
        const uint32_t ca_h = (uint32_t)__cvta_generic_to_shared(xb + arow);
        const uint32_t ca_l = ca_h + 16 * XP * 4;

        float acc1[4][4], acc2[4][4];
        #pragma unroll
        for (int j = 0; j < 4; j++)
            #pragma unroll
            for (int r = 0; r < 4; r++) { acc1[j][r] = 0.f; acc2[j][r] = 0.f; }

        #pragma unroll
        for (int p = 0; p < 2; p++) {
            float (*acc)[4] = p ? acc2 : acc1;
            #pragma unroll
            for (int kc = 0; kc < 8; kc++) {
                uint32_t ah0, ah1, ah2, ah3, al0, al1, al2, al3;
                ldsm4(ah0, ah1, ah2, ah3, ca_h + kc * 32);
                ldsm4(al0, al1, al2, al3, ca_l + kc * 32);
                #pragma unroll
                for (int j = 0; j < 4; j++) {
                    const int ntg = nh * 4 + j;
                    uint2 bq = g_W23pack[((p * 16 + ntg) * 8 + kc) * 32 + lane];
                    mma_f16(acc[j], ah0, ah1, ah2, ah3, bq.x, bq.y);
                    mma_f16(acc[j], al0, al1, al2, al3, bq.x, bq.y);
                }
            }
        }
        // extract: k = g (g<4), x2 = acc1 row g, wms = acc2 row g+4 (lane+16)
        // csg holds 0.5*(c + b1) (bias folded; x2 stays bias-free)
        #pragma unroll
        for (int j = 0; j < 4; j++)
            #pragma unroll
            for (int c2 = 0; c2 < 2; c2++) {
                float wmsv = __shfl_down_sync(0xffffffffu, acc2[j][c2], 16);
                if (g < 4) {
                    int h = (nh * 4 + j) * 8 + 2 * qc + c2;
                    float bv = w1_b[h];
                    x2g[g * 128 + h] = acc1[j][c2];
                    csg[g * 128 + h] = 0.5f * (acc1[j][c2] + wmsv + bv);
                }
            }
    }
    barg(bar);   // cs/x2 visible; c-phase ldsm done (buffer reusable)

    float hacc[K_LAB][4][2];
    float sp[K_LAB];
    #pragma unroll
    for (int k = 0; k < K_LAB; k++) {
        sp[k] = 0.f;
        #pragma unroll
        for (int nt = 0; nt < 4; nt++) { hacc[k][nt][0] = 0.f; hacc[k][nt][1] = 0.f; }
    }

    const int n_tiles = (len + S_TILE - 1) >> 5;
    const uint32_t sa_h = (uint32_t)__cvta_generic_to_shared(xb + arow);

    const int srow = local >> 2;     // staging row 0..31 (4 threads/row)
    const int f4c  = local & 3;

    // ================= group tile loop: ALL tiles of this group's batch =================
    for (int t = 0; t < n_tiles; t++) {
        const int s0 = t * S_TILE;

        // ---- stage: coalesced LDG + single fp16 convert + STS into group buffer ----
        {
            const int gs = s0 + srow;
            const bool vld = (gs < len);
            const float4* src = reinterpret_cast<const float4*>(
                inputs + (size_t)gs * BI + (size_t)b * I_DIM);
            #pragma unroll
            for (int j = 0; j < 8; j++) {
                const int c4 = j * 4 + f4c;          // coalesced per j
                float4 x = vld ? src[c4] : make_float4(0.f, 0.f, 0.f, 0.f);
                uint32_t h0 = pack_f16x2(x.x, x.y);
                uint32_t h1 = pack_f16x2(x.z, x.w);
                *reinterpret_cast<uint2*>(xb + srow * XP + c4 * 2) = make_uint2(h0, h1);
            }
        }
        barg(bar);

        // ---- single-pass fp16 MMA: warp tile 32s x 32h, zero-seeded (bias folded out) ----
        float x1f[2][4][4];
        #pragma unroll
        for (int mt = 0; mt < 2; mt++)
            #pragma unroll
            for (int nt = 0; nt < 4; nt++)
                #pragma unroll
                for (int r = 0; r < 4; r++) x1f[mt][nt][r] = 0.f;

        #pragma unroll
        for (int kc = 0; kc < 8; kc++) {
            uint32_t ah[2][4];
            #pragma unroll
            for (int mt = 0; mt < 2; mt++) {
                const uint32_t off = (uint32_t)(mt * 16 * XP * 4 + kc * 32);
                ldsm4(ah[mt][0], ah[mt][1], ah[mt][2], ah[mt][3], sa_h + off);
            }
            #pragma unroll
            for (int nt = 0; nt < 4; nt++) {
                uint2 bq = wp2[((nh * 4 + nt) * 8 + kc) * 32 + lane];
                #pragma unroll
                for (int mt = 0; mt < 2; mt++)
                    mma_f16(x1f[mt][nt], ah[mt][0], ah[mt][1], ah[mt][2], ah[mt][3], bq.x, bq.y);
            }
        }

        // ---- sigmoid (tanh form, single-FFMA z; bias inside csg) + w0 partial sums ----
        #pragma unroll
        for (int k = 0; k < K_LAB; k++) {
            const int tk = start + k;
            if (k < nk && s0 <= tk) {
                float ps[2][2];
                ps[0][0] = w0s; ps[0][1] = w0s; ps[1][0] = w0s; ps[1][1] = w0s;
                #pragma unroll
                for (int nt = 0; nt < 4; nt++) {
                    float2 cv = *reinterpret_cast<const float2*>(
                        &csg[k * 128 + nh * 32 + nt * 8 + 2 * qc]);   // 0.5*(c+b1)
                    #pragma unroll
                    for (int mt = 0; mt < 2; mt++) {
                        ps[mt][0] += w0h[nt][0] * tanhf_fast(fmaf(0.5f, x1f[mt][nt][0], cv.x))
                                   + w0h[nt][1] * tanhf_fast(fmaf(0.5f, x1f[mt][nt][1], cv.y));
                        ps[mt][1] += w0h[nt][0] * tanhf_fast(fmaf(0.5f, x1f[mt][nt][2], cv.x))
                                   + w0h[nt][1] * tanhf_fast(fmaf(0.5f, x1f[mt][nt][3], cv.y));
                    }
                }
                #pragma unroll
                for (int mt = 0; mt < 2; mt++)
                    #pragma unroll
                    for (int r = 0; r < 2; r++) {
                        float v = ps[mt][r];
                        v += __shfl_xor_sync(0xffffffffu, v, 1);
                        v += __shfl_xor_sync(0xffffffffu, v, 2);
                        ps[mt][r] = v;
                    }
                if (qc == 0) {
                    #pragma unroll
                    for (int mt = 0; mt < 2; mt++) {
                        pbg[(k * 32 + mt * 16 + g) * 4 + nh]     = ps[mt][0];
                        pbg[(k * 32 + mt * 16 + g + 8) * 4 + nh] = ps[mt][1];
                    }
                }
            }
        }
        barg(bar);

        // ---- read total p, mask, accumulate h (x1 is bias-free; b1 term via sp) ----
        const float4* pb4 = reinterpret_cast<const float4*>(pbg);
        #pragma unroll
        for (int k = 0; k < K_LAB; k++) {
            const int tk = start + k;
            if (k < nk && s0 <= tk) {
                #pragma unroll
                for (int mt = 0; mt < 2; mt++) {
                    const int r0 = mt * 16 + g;
                    float4 p0 = pb4[k * 32 + r0];
                    float4 p1 = pb4[k * 32 + r0 + 8];
                    float pt0 = (s0 + r0     <= tk) ? (p0.x + p0.y + p0.z + p0.w) : 0.f;
                    float pt1 = (s0 + r0 + 8 <= tk) ? (p1.x + p1.y + p1.z + p1.w) : 0.f;
                    sp[k] += pt0 + pt1;
                    #pragma unroll
                    for (int nt = 0; nt < 4; nt++) {
                        hacc[k][nt][0] += pt0 * x1f[mt][nt][0] + pt1 * x1f[mt][nt][2];
                        hacc[k][nt][1] += pt0 * x1f[mt][nt][1] + pt1 * x1f[mt][nt][3];
                    }
                }
            }
        }
        // next stage / pb write only after the next barg -> safe
    }

    // ---- reduce hacc and sp over row groups (butterfly), direct output ----
    #pragma unroll
    for (int k = 0; k < K_LAB; k++) {
        float v = sp[k];
        v += __shfl_xor_sync(0xffffffffu, v, 4);
        v += __shfl_xor_sync(0xffffffffu, v, 8);
        v += __shfl_xor_sync(0xffffffffu, v, 16);
        sp[k] = v;
        #pragma unroll
        for (int nt = 0; nt < 4; nt++)
            #pragma unroll
            for (int c = 0; c < 2; c++) {
                float u = hacc[k][nt][c];
                u += __shfl_xor_sync(0xffffffffu, u, 4);
                u += __shfl_xor_sync(0xffffffffu, u, 8);
                u += __shfl_xor_sync(0xffffffffu, u, 16);
                hacc[k][nt][c] = u;
            }
    }

    // lane with g == k writes row k of this batch's output (8 values per lane: nt x c)
    float* ob = out + (size_t)b * (K_LAB * H_DIM);
    #pragma unroll
    for (int k = 0; k < K_LAB; k++) {
        if (g == k) {
            #pragma unroll
            for (int nt = 0; nt < 4; nt++)
                #pragma unroll
                for (int c = 0; c < 2; c++) {
                    int h = nh * 32 + nt * 8 + 2 * qc + c;
                    float v = 0.f;
                    if (k < nk)
                        v = hacc[k][nt][c] + sp[k] * w1_b[h] + x2g[k * 128 + h];
                    ob[k * 128 + h] = v;
                }
        }
    }
}

extern "C" void kernel_launch(void* const* d_in, const int* in_sizes, int n_in,
                              void* d_out, int out_size)
{
    // input order: inputs, lengths, [label_len], w0, w1_w, w1_b, w2_w, w3_w
    const int base = (n_in >= 8) ? 3 : 2;
    const float* inputs  = (const float*)d_in[0];
    const int*   lengths = (const int*)d_in[1];
    const float* w0   = (const float*)d_in[base + 0];
    const float* w1_w = (const float*)d_in[base + 1];
    const float* w1_b = (const float*)d_in[base + 2];
    const float* w2_w = (const float*)d_in[base + 3];
    const float* w3_w = (const float*)d_in[base + 4];
    float* out = (float*)d_out;

    pack_kernel<<<48, 256>>>(w1_w, w2_w, w3_w);   // 12288 entries

    const size_t smem_bytes = (size_t)SM_TOT * sizeof(float);
    cudaFuncSetAttribute(fused_r15_kernel,
                         cudaFuncAttributeMaxDynamicSharedMemorySize,
                         (int)smem_bytes);
    fused_r15_kernel<<<GRID, THREADS, smem_bytes>>>(inputs, lengths, w0, w1_b, out);
}

// round 16
// speedup vs baseline: 1.2474x; 1.2474x over previous
#include <cuda_runtime.h>
#include <cuda_fp16.h>
#include <cstdint>

#define T_DIM 200
#define B_DIM 2048
#define I_DIM 128
#define H_DIM 128
#define K_LAB 4
#define S_TILE 32
#define GRID   304             // persistent: ~2 CTAs/SM, single wave
#define THREADS 256
#define XP     68              // pair-row stride (u32 words): conflict-free A-frag reads
#define BI     (B_DIM * I_DIM)

// ---- shared memory layout (4-byte word offsets) ----
// WP shared by both groups; everything else per group (stride GW)
#define SM_WP   0               // 16*8*32 uint2 = 8192 words (32 KB W1 pack, fp16)
#define GW      4752            // per-group region size (incl. work slot)
#define G_XB    0               // 2176: staging / c-phase A-tile (hi rows 0-15, lo rows 16-31)
#define G_PB    2176            // 512: p exchange
#define G_CS    2688            // 512 (holds 0.5*c)
#define G_X2    3200            // 512
#define G_XL    3712            // 512
#define G_XM    4224            // 512
#define G_BS    4736            // 16: work-index slot
#define SM_TOT  (8192 + 2*GW)   // 17696 words = 70784 B

#define W1_FRAGS  (16 * 8 * 32)    // 4096
#define W23_FRAGS (2 * 16 * 8 * 32)

// W1 packed as fp16 B fragments: [nt(16)][kc(8)][lane(32)] -> (wh0, wh1)
__device__ uint2 g_Wpack[W1_FRAGS];
// W2 (pass 0) and W3 (pass 1) packed the same way: [p(2)][nt(16)][kc(8)][lane(32)]
__device__ uint2 g_W23pack[W23_FRAGS];
// work-stealing counter (reset by pack_kernel each launch)
__device__ int g_counter;

__device__ __forceinline__ uint32_t pack_f16x2(float e_even, float e_odd) {
    uint32_t r;
    asm("cvt.rn.f16x2.f32 %0, %1, %2;" : "=r"(r) : "f"(e_odd), "f"(e_even));
    return r;
}
__device__ __forceinline__ float2 unpack_f16x2(uint32_t u) {
    __half2 h = *reinterpret_cast<__half2*>(&u);
    return __half22float2(h);
}
__device__ __forceinline__ float tanhf_fast(float z) {
    float t;
    asm("tanh.approx.f32 %0, %1;" : "=f"(t) : "f"(z));
    return t;
}
__device__ __forceinline__ void mma_f16(float* c,
                                        uint32_t a0, uint32_t a1, uint32_t a2, uint32_t a3,
                                        uint32_t b0, uint32_t b1) {
    asm volatile(
        "mma.sync.aligned.m16n8k16.row.col.f32.f16.f16.f32 "
        "{%0,%1,%2,%3}, {%4,%5,%6,%7}, {%8,%9}, {%0,%1,%2,%3};"
        : "+f"(c[0]), "+f"(c[1]), "+f"(c[2]), "+f"(c[3])
        : "r"(a0), "r"(a1), "r"(a2), "r"(a3), "r"(b0), "r"(b1));
}
__device__ __forceinline__ void ldsm4(uint32_t& r0, uint32_t& r1, uint32_t& r2,
                                      uint32_t& r3, uint32_t a) {
    asm volatile("ldmatrix.sync.aligned.m8n8.x4.shared.b16 {%0,%1,%2,%3}, [%4];"
                 : "=r"(r0), "=r"(r1), "=r"(r2), "=r"(r3) : "r"(a));
}
__device__ __forceinline__ void barg(int id) {
    asm volatile("bar.sync %0, 128;" :: "r"(id) : "memory");
}

// ---------------- pack kernel: W1/W2/W3 -> fp16 B-fragment layouts (+ counter reset) ----------------
__global__ void pack_kernel(const float* __restrict__ w1_w,
                            const float* __restrict__ w2_w,
                            const float* __restrict__ w3_w) {
    int idx = blockIdx.x * blockDim.x + threadIdx.x;   // 0 .. W1_FRAGS + W23_FRAGS - 1
    if (idx == 0) g_counter = 0;
    if (idx >= W1_FRAGS + W23_FRAGS) return;

    const float* src;
    uint2* dst;
    int kc, lane, nt;
    if (idx < W1_FRAGS) {             // W1: [nt(16)][kc(8)][lane(32)]
        lane = idx & 31; kc = (idx >> 5) & 7; nt = (idx >> 8) & 15;
        src = w1_w; dst = g_Wpack + idx;
    } else {                          // W2/W3: [p(2)][nt(16)][kc(8)][lane(32)]
        int i2 = idx - W1_FRAGS;
        lane = i2 & 31; kc = (i2 >> 5) & 7; nt = (i2 >> 8) & 15;
        int p = i2 >> 12;
        src = p ? w3_w : w2_w;
        dst = g_W23pack + i2;
    }
    int n  = nt * 8 + (lane >> 2);
    int k0 = kc * 16 + 2 * (lane & 3);
    const float* wr = src + n * I_DIM;
    uint2 v;
    v.x = pack_f16x2(wr[k0],     wr[k0 + 1]);
    v.y = pack_f16x2(wr[k0 + 8], wr[k0 + 9]);
    *dst = v;
}

// ---------------- main fused kernel (persistent, work-stealing groups) ----------------
__global__ void __launch_bounds__(THREADS, 2)
fused_r16_kernel(const float* __restrict__ inputs,
                 const int*   __restrict__ lengths,
                 const float* __restrict__ w0,
                 const float* __restrict__ w1_b,
                 float* __restrict__ out)
{
    extern __shared__ float sm[];
    uint32_t* smu = reinterpret_cast<uint32_t*>(sm);

    const int tid   = threadIdx.x;
    const int lane  = tid & 31;
    const int grp   = tid >> 7;          // group 0/1: independent batch pipeline
    const int nh    = (tid >> 5) & 3;    // warp within group: h quarter
    const int g     = lane >> 2;         // row group 0..7
    const int qc    = lane & 3;          // col class 0..3
    const int local = tid & 127;         // index within group

    // per-group smem regions
    float*    gbase = sm + 8192 + grp * GW;
    uint32_t* xb    = smu + 8192 + grp * GW + G_XB;
    float*    pbg   = gbase + G_PB;
    float*    csg   = gbase + G_CS;
    float*    x2g   = gbase + G_X2;
    float*    xlg   = gbase + G_XL;
    float*    xmg   = gbase + G_XM;
    volatile int* bslot = reinterpret_cast<volatile int*>(gbase + G_BS);
    const int bar   = 1 + grp;

    // ---- copy packed W1 into smem (both groups cooperate; 2048 uint4) ----
    uint4* wp4g = reinterpret_cast<uint4*>(g_Wpack);
    uint4* wp4s = reinterpret_cast<uint4*>(smu + SM_WP);
    #pragma unroll
    for (int i = 0; i < 8; i++)
        wp4s[tid + i * THREADS] = wp4g[tid + i * THREADS];
    const uint2* wp2 = reinterpret_cast<const uint2*>(smu + SM_WP);

    // ---- hoist w0 (pre-halved) / bias fragments ----
    float w0h[4][2], b1r[4][2];
    float w0s = 0.f;
    #pragma unroll
    for (int nt = 0; nt < 4; nt++)
        #pragma unroll
        for (int c = 0; c < 2; c++) {
            int h = nh * 32 + nt * 8 + 2 * qc + c;
            w0h[nt][c] = 0.5f * w0[h];
            w0s += w0h[nt][c];
            b1r[nt][c] = w1_b[h];
        }

    // ldmatrix lane address pattern (word offset within a 32-row buffer)
    const uint32_t arow = (uint32_t)((lane & 15) * XP + (lane >> 4) * 4);
    const uint32_t sa_h = (uint32_t)__cvta_generic_to_shared(xb + arow);
    const int srow = local >> 2;     // staging row 0..31 (4 threads/row)
    const int f4c  = local & 3;

    __syncthreads();   // W pack visible to both groups (only cross-group sync)

    // ================= persistent work loop: one batch per iteration =================
    for (;;) {
        if (local == 0)
            *bslot = atomicAdd(&g_counter, 1);
        barg(bar);
        const int b = *bslot;
        if (b >= B_DIM) break;

        const int len   = lengths[b];
        const int start = max(len - K_LAB, 0);
        const int nk    = min(len, K_LAB);

        // ---- prefix sum + labeled snapshots: one thread per feature, register-only ----
        {
            const int i = local;
            const float* ip = inputs + (size_t)b * I_DIM + i;
            float a0 = 0.f, a1 = 0.f, a2 = 0.f, a3 = 0.f;
            float a4 = 0.f, a5 = 0.f, a6 = 0.f, a7 = 0.f;
            int s = 0;
            for (; s + 8 <= start; s += 8) {
                a0 += ip[(size_t)(s    ) * BI];
                a1 += ip[(size_t)(s + 1) * BI];
                a2 += ip[(size_t)(s + 2) * BI];
                a3 += ip[(size_t)(s + 3) * BI];
                a4 += ip[(size_t)(s + 4) * BI];
                a5 += ip[(size_t)(s + 5) * BI];
                a6 += ip[(size_t)(s + 6) * BI];
                a7 += ip[(size_t)(s + 7) * BI];
            }
            float acc = ((a0 + a1) + (a2 + a3)) + ((a4 + a5) + (a6 + a7));
            for (; s < start; s++)
                acc += ip[(size_t)s * BI];
            #pragma unroll
            for (int k = 0; k < K_LAB; k++) {
                float xv = 0.f, mv = 0.f;
                if (k < nk) {
                    xv = ip[(size_t)(start + k) * BI];
                    acc += xv;
                    mv = acc / (float)(start + k + 1);
                }
                xlg[k * 128 + i] = xv;
                xmg[k * 128 + i] = mv;
            }
        }
        barg(bar);

        // ---- build c-phase A tile: hi rows 0-15, lo rows 16-31 ----
        {
            const int r   = local >> 4;          // 0..7
            const int t16 = local & 15;
            #pragma unroll
            for (int u = 0; u < 2; u++) {
                const int t32 = t16 * 2 + u;
                const float4 v = *reinterpret_cast<const float4*>(
                    &(r < 4 ? xlg[r * 128] : xmg[(r - 4) * 128]) + t32 * 4);
                uint32_t h0 = pack_f16x2(v.x, v.y);
                uint32_t h1 = pack_f16x2(v.z, v.w);
                float2 f0 = unpack_f16x2(h0);
                float2 f1 = unpack_f16x2(h1);
                uint32_t l0 = pack_f16x2(v.x - f0.x, v.y - f0.y);
                uint32_t l1 = pack_f16x2(v.z - f1.x, v.w - f1.y);
                int p = r * XP + t32 * 2;
                *reinterpret_cast<uint2*>(xb + p)           = make_uint2(h0, h1);
                *reinterpret_cast<uint2*>(xb + 16 * XP + p) = make_uint2(l0, l1);
                int z = (8 + r) * XP + t32 * 2;
                *reinterpret_cast<uint2*>(xb + z)           = make_uint2(0u, 0u);
                *reinterpret_cast<uint2*>(xb + 16 * XP + z) = make_uint2(0u, 0u);
            }
        }
        barg(bar);

        // ---- c[k][h] via MMA (2-pass hi/lo A): pass0 B=W2 (-> x2), pass1 B=W3 ----
        {
            const uint32_t ca_h = sa_h;
            const uint32_t ca_l = ca_h + 16 * XP * 4;

            float acc1[4][4], acc2[4][4];
            #pragma unroll
            for (int j = 0; j < 4; j++)
                #pragma unroll
                for (int r = 0; r < 4; r++) { acc1[j][r] = 0.f; acc2[j][r] = 0.f; }

            #pragma unroll
            for (int p = 0; p < 2; p++) {
                float (*acc)[4] = p ? acc2 : acc1;
                #pragma unroll
                for (int kc = 0; kc < 8; kc++) {
                    uint32_t ah0, ah1, ah2, ah3, al0, al1, al2, al3;
                    ldsm4(ah0, ah1, ah2, ah3, ca_h + kc * 32);
                    ldsm4(al0, al1, al2, al3, ca_l + kc * 32);
                    #pragma unroll
                    for (int j = 0; j < 4; j++) {
                        const int ntg = nh * 4 + j;
                        uint2 bq = g_W23pack[((p * 16 + ntg) * 8 + kc) * 32 + lane];
                        mma_f16(acc[j], ah0, ah1, ah2, ah3, bq.x, bq.y);
                        mma_f16(acc[j], al0, al1, al2, al3, bq.x, bq.y);
                    }
                }
            }
            // extract: k = g (g<4), x2 = acc1 row g, wms = acc2 row g+4 (lane+16)
            // csg holds 0.5*c
            #pragma unroll
            for (int j = 0; j < 4; j++)
                #pragma unroll
                for (int c2 = 0; c2 < 2; c2++) {
                    float wmsv = __shfl_down_sync(0xffffffffu, acc2[j][c2], 16);
                    if (g < 4) {
                        int h = (nh * 4 + j) * 8 + 2 * qc + c2;
                        x2g[g * 128 + h] = acc1[j][c2];
                        csg[g * 128 + h] = 0.5f * (acc1[j][c2] + wmsv);
                    }
                }
        }
        barg(bar);   // cs/x2 visible; c-phase ldsm done (buffer reusable)

        float hacc[K_LAB][4][2];
        #pragma unroll
        for (int k = 0; k < K_LAB; k++)
            #pragma unroll
            for (int nt = 0; nt < 4; nt++) { hacc[k][nt][0] = 0.f; hacc[k][nt][1] = 0.f; }

        const int n_tiles = (len + S_TILE - 1) >> 5;

        // ---- tile loop ----
        for (int t = 0; t < n_tiles; t++) {
            const int s0 = t * S_TILE;

            // stage: coalesced LDG + single fp16 convert + STS
            {
                const int gs = s0 + srow;
                const bool vld = (gs < len);
                const float4* src = reinterpret_cast<const float4*>(
                    inputs + (size_t)gs * BI + (size_t)b * I_DIM);
                #pragma unroll
                for (int j = 0; j < 8; j++) {
                    const int c4 = j * 4 + f4c;
                    float4 x = vld ? src[c4] : make_float4(0.f, 0.f, 0.f, 0.f);
                    uint32_t h0 = pack_f16x2(x.x, x.y);
                    uint32_t h1 = pack_f16x2(x.z, x.w);
                    *reinterpret_cast<uint2*>(xb + srow * XP + c4 * 2) = make_uint2(h0, h1);
                }
            }
            barg(bar);

            // single-pass fp16 MMA: warp tile 32s x 32h, bias-seeded accumulators
            float x1f[2][4][4];
            #pragma unroll
            for (int mt = 0; mt < 2; mt++)
                #pragma unroll
                for (int nt = 0; nt < 4; nt++) {
                    x1f[mt][nt][0] = b1r[nt][0];
                    x1f[mt][nt][1] = b1r[nt][1];
                    x1f[mt][nt][2] = b1r[nt][0];
                    x1f[mt][nt][3] = b1r[nt][1];
                }

            #pragma unroll
            for (int kc = 0; kc < 8; kc++) {
                uint32_t ah[2][4];
                #pragma unroll
                for (int mt = 0; mt < 2; mt++) {
                    const uint32_t off = (uint32_t)(mt * 16 * XP * 4 + kc * 32);
                    ldsm4(ah[mt][0], ah[mt][1], ah[mt][2], ah[mt][3], sa_h + off);
                }
                #pragma unroll
                for (int nt = 0; nt < 4; nt++) {
                    uint2 bq = wp2[((nh * 4 + nt) * 8 + kc) * 32 + lane];
                    #pragma unroll
                    for (int mt = 0; mt < 2; mt++)
                        mma_f16(x1f[mt][nt], ah[mt][0], ah[mt][1], ah[mt][2], ah[mt][3], bq.x, bq.y);
                }
            }

            // sigmoid (tanh form, single-FFMA z) + w0 partial sums
            #pragma unroll
            for (int k = 0; k < K_LAB; k++) {
                const int tk = start + k;
                if (k < nk && s0 <= tk) {
                    float ps[2][2];
                    ps[0][0] = w0s; ps[0][1] = w0s; ps[1][0] = w0s; ps[1][1] = w0s;
                    #pragma unroll
                    for (int nt = 0; nt < 4; nt++) {
                        float2 cv = *reinterpret_cast<const float2*>(
                            &csg[k * 128 + nh * 32 + nt * 8 + 2 * qc]);   // 0.5*c
                        #pragma unroll
                        for (int mt = 0; mt < 2; mt++) {
                            ps[mt][0] += w0h[nt][0] * tanhf_fast(fmaf(0.5f, x1f[mt][nt][0], cv.x))
                                       + w0h[nt][1] * tanhf_fast(fmaf(0.5f, x1f[mt][nt][1], cv.y));
                            ps[mt][1] += w0h[nt][0] * tanhf_fast(fmaf(0.5f, x1f[mt][nt][2], cv.x))
                                       + w0h[nt][1] * tanhf_fast(fmaf(0.5f, x1f[mt][nt][3], cv.y));
                        }
                    }
                    #pragma unroll
                    for (int mt = 0; mt < 2; mt++)
                        #pragma unroll
                        for (int r = 0; r < 2; r++) {
                            float v = ps[mt][r];
                            v += __shfl_xor_sync(0xffffffffu, v, 1);
                            v += __shfl_xor_sync(0xffffffffu, v, 2);
                            ps[mt][r] = v;
                        }
                    if (qc == 0) {
                        #pragma unroll
                        for (int mt = 0; mt < 2; mt++) {
                            pbg[(k * 32 + mt * 16 + g) * 4 + nh]     = ps[mt][0];
                            pbg[(k * 32 + mt * 16 + g + 8) * 4 + nh] = ps[mt][1];
                        }
                    }
                }
            }
            barg(bar);

            // read total p, mask, accumulate h
            const float4* pb4 = reinterpret_cast<const float4*>(pbg);
            #pragma unroll
            for (int k = 0; k < K_LAB; k++) {
                const int tk = start + k;
                if (k < nk && s0 <= tk) {
                    #pragma unroll
                    for (int mt = 0; mt < 2; mt++) {
                        const int r0 = mt * 16 + g;
                        float4 p0 = pb4[k * 32 + r0];
                        float4 p1 = pb4[k * 32 + r0 + 8];
                        float pt0 = (s0 + r0     <= tk) ? (p0.x + p0.y + p0.z + p0.w) : 0.f;
                        float pt1 = (s0 + r0 + 8 <= tk) ? (p1.x + p1.y + p1.z + p1.w) : 0.f;
                        #pragma unroll
                        for (int nt = 0; nt < 4; nt++) {
                            hacc[k][nt][0] += pt0 * x1f[mt][nt][0] + pt1 * x1f[mt][nt][2];
                            hacc[k][nt][1] += pt0 * x1f[mt][nt][1] + pt1 * x1f[mt][nt][3];
                        }
                    }
                }
            }
            // next stage / pb write only after the next barg -> safe
        }

        // ---- reduce hacc over row groups (butterfly -> all lanes), direct output ----
        #pragma unroll
        for (int k = 0; k < K_LAB; k++)
            #pragma unroll
            for (int nt = 0; nt < 4; nt++)
                #pragma unroll
                for (int c = 0; c < 2; c++) {
                    float v = hacc[k][nt][c];
                    v += __shfl_xor_sync(0xffffffffu, v, 4);
                    v += __shfl_xor_sync(0xffffffffu, v, 8);
                    v += __shfl_xor_sync(0xffffffffu, v, 16);
                    hacc[k][nt][c] = v;
                }

        // lane with g == k writes row k of this batch's output
        float* ob = out + (size_t)b * (K_LAB * H_DIM);
        #pragma unroll
        for (int k = 0; k < K_LAB; k++) {
            if (g == k) {
                #pragma unroll
                for (int nt = 0; nt < 4; nt++)
                    #pragma unroll
                    for (int c = 0; c < 2; c++) {
                        int h = nh * 32 + nt * 8 + 2 * qc + c;
                        float v = 0.f;
                        if (k < nk)
                            v = hacc[k][nt][c] + x2g[k * 128 + h];
                        ob[k * 128 + h] = v;
                    }
            }
        }
        barg(bar);   // batch complete; safe to fetch next work item
    }
}

extern "C" void kernel_launch(void* const* d_in, const int* in_sizes, int n_in,
                              void* d_out, int out_size)
{
    // input order: inputs, lengths, [label_len], w0, w1_w, w1_b, w2_w, w3_w
    const int base = (n_in >= 8) ? 3 : 2;
    const float* inputs  = (const float*)d_in[0];
    const int*   lengths = (const int*)d_in[1];
    const float* w0   = (const float*)d_in[base + 0];
    const float* w1_w = (const float*)d_in[base + 1];
    const float* w1_b = (const float*)d_in[base + 2];
    const float* w2_w = (const float*)d_in[base + 3];
    const float* w3_w = (const float*)d_in[base + 4];
    float* out = (float*)d_out;

    pack_kernel<<<48, 256>>>(w1_w, w2_w, w3_w);   // 12288 entries + counter reset

    const size_t smem_bytes = (size_t)SM_TOT * sizeof(float);
    cudaFuncSetAttribute(fused_r16_kernel,
                         cudaFuncAttributeMaxDynamicSharedMemorySize,
                         (int)smem_bytes);
    fused_r16_kernel<<<GRID, THREADS, smem_bytes>>>(inputs, lengths, w0, w1_b, out);
}